// round 3
// baseline (speedup 1.0000x reference)
#include <cuda_runtime.h>
#include <cuda_bf16.h>
#include <cstdint>

#define MAXL 16
#define S    16          // argmax slices per request
#define TPB2 256         // threads for the streaming kernel
#define MAXB 1024        // max requests supported by scratch

// Scratch (no device allocation allowed). Every k2 block writes its own slot
// unconditionally, so no reset pass is needed across graph replays.
__device__ unsigned long long g_slot[MAXB * S];
__device__ int4               g_meta[MAXB];   // x=rejected, y=rec_row, z=write_col

// ---------------------------------------------------------------------------
// k1: per-request gather + acceptance scan; writes meta and the base output row
// ---------------------------------------------------------------------------
__global__ void __launch_bounds__(64)
k1_scan(const float* __restrict__ draft_probs,
        const float* __restrict__ target_probs,
        const float* __restrict__ uniform_probs,
        const int*   __restrict__ draft_token_ids,
        const int*   __restrict__ cu,
        const int*   __restrict__ bonus,
        float*       __restrict__ out,
        int V, int NT, int L)
{
    const int b   = blockIdx.x;
    const int tid = threadIdx.x;

    __shared__ int   s_dids[MAXL];
    __shared__ float s_tp[MAXL], s_dp[MAXL], s_u[MAXL];
    __shared__ int   s_last, s_rejected, s_write_col;

    const int prev   = (b == 0) ? 0 : cu[b - 1];
    const int ndraft = cu[b] - prev;
    const int n      = ndraft < L ? ndraft : L;

    if (tid < n && n > 0) {
        long long gidx = (long long)(prev + tid);
        int d = __ldg(&draft_token_ids[gidx]);
        s_dids[tid] = d;
        s_tp[tid] = __ldg(&target_probs[gidx * (long long)V + d]);
        s_dp[tid] = __ldg(&draft_probs [gidx * (long long)V + d]);
        s_u [tid] = __ldg(&uniform_probs[gidx]);
    }
    __syncthreads();

    if (tid == 0) {
        float pi = 1.0f, U = 1.0f;
        int last = -1;
        for (int i = 0; i < n; i++) {
            float dp = s_dp[i];
            float r  = (dp > 0.0f) ? (s_tp[i] / dp) : 1.0f;
            pi = fminf(pi * r, 1.0f);
            U  = U * s_u[i];
            if ((dp > 0.0f) && (pi >= U)) last = i;
        }
        int rejected = (ndraft > 0) && (last != ndraft - 1);
        int rec_row  = prev + last + 1;
        rec_row = max(0, min(rec_row, NT - 1));
        s_last      = last;
        s_rejected  = rejected;
        s_write_col = rejected ? (last + 1) : n;
        g_meta[b] = make_int4(rejected, rec_row, s_write_col, 0);
    }
    __syncthreads();

    if (tid <= L) {
        int val = (tid < L && tid <= s_last) ? s_dids[tid] : -1;
        if (tid == s_write_col)
            val = s_rejected ? -1 : bonus[b];   // rejected slot patched by k3
        out[b * (L + 1) + tid] = (float)val;
    }
}

// ---------------------------------------------------------------------------
// k2: sliced argmax. blockIdx = (slice, request). Packed key:
//   (float_bits << 32) | (0xFFFFFFFF - idx)  -> max key == first max value
// (softmax probs >= 0, so the fp32 bit pattern is order-preserving).
// ---------------------------------------------------------------------------
__global__ void __launch_bounds__(TPB2)
k2_argmax_slice(const float* __restrict__ target_probs, int V)
{
    const int s   = blockIdx.x;
    const int b   = blockIdx.y;
    const int tid = threadIdx.x;

    __shared__ unsigned long long s_warp[TPB2 / 32];

    const int4 meta = g_meta[b];
    if (!meta.x) {                       // not rejected: publish neutral slot
        if (tid == 0) g_slot[b * S + s] = 0ull;
        return;
    }

    // Slice bounds, rounded so each slice start is float4-aligned.
    const int chunk = (((V + S - 1) / S) + 3) & ~3;
    const int start = s * chunk;
    const int end   = min(V, start + chunk);

    const float* __restrict__ row = target_probs + (long long)meta.y * V;

    unsigned long long best = 0ull;
    int i = start + tid * 4;
    // float4 main loop (start is 4-aligned; row base is 16B-aligned)
    for (; i + 3 < end; i += TPB2 * 4) {
        float4 v = *(const float4*)(row + i);
        unsigned long long k;
        k = ((unsigned long long)__float_as_uint(v.x) << 32) | (0xFFFFFFFFu - (unsigned)i);
        if (k > best) best = k;
        k = ((unsigned long long)__float_as_uint(v.y) << 32) | (0xFFFFFFFFu - (unsigned)(i + 1));
        if (k > best) best = k;
        k = ((unsigned long long)__float_as_uint(v.z) << 32) | (0xFFFFFFFFu - (unsigned)(i + 2));
        if (k > best) best = k;
        k = ((unsigned long long)__float_as_uint(v.w) << 32) | (0xFFFFFFFFu - (unsigned)(i + 3));
        if (k > best) best = k;
    }
    // scalar tail
    for (; i < end; i++) {
        unsigned long long k =
            ((unsigned long long)__float_as_uint(row[i]) << 32) |
            (0xFFFFFFFFu - (unsigned)i);
        if (k > best) best = k;
    }

    #pragma unroll
    for (int off = 16; off > 0; off >>= 1) {
        unsigned long long o = __shfl_down_sync(0xFFFFFFFFu, best, off);
        if (o > best) best = o;
    }
    if ((tid & 31) == 0) s_warp[tid >> 5] = best;
    __syncthreads();

    if (tid < 32) {
        unsigned long long v = (tid < (TPB2 / 32)) ? s_warp[tid] : 0ull;
        #pragma unroll
        for (int off = 16; off > 0; off >>= 1) {
            unsigned long long o = __shfl_down_sync(0xFFFFFFFFu, v, off);
            if (o > v) v = o;
        }
        if (tid == 0) g_slot[b * S + s] = v;
    }
}

// ---------------------------------------------------------------------------
// k3: reduce S slots per request; patch the recovered-token output element.
// ---------------------------------------------------------------------------
__global__ void __launch_bounds__(32)
k3_finalize(float* __restrict__ out, int L)
{
    const int b   = blockIdx.x;
    const int tid = threadIdx.x;

    const int4 meta = g_meta[b];
    if (!meta.x) return;

    unsigned long long v = (tid < S) ? g_slot[b * S + tid] : 0ull;
    #pragma unroll
    for (int off = 16; off > 0; off >>= 1) {
        unsigned long long o = __shfl_down_sync(0xFFFFFFFFu, v, off);
        if (o > v) v = o;
    }
    if (tid == 0) {
        int rec = (int)(0xFFFFFFFFu - (unsigned)(v & 0xFFFFFFFFull));
        out[b * (L + 1) + meta.z] = (float)rec;
    }
}

extern "C" void kernel_launch(void* const* d_in, const int* in_sizes, int n_in,
                              void* d_out, int out_size) {
    const float* draft_probs     = (const float*)d_in[0];
    const float* target_probs    = (const float*)d_in[1];
    const float* uniform_probs   = (const float*)d_in[2];
    const int*   draft_token_ids = (const int*)  d_in[3];
    const int*   cu              = (const int*)  d_in[4];
    const int*   bonus           = (const int*)  d_in[5];
    float*       out             = (float*)d_out;

    const int NT = in_sizes[2];
    const int V  = in_sizes[0] / NT;
    const int B  = in_sizes[4];
    const int L  = out_size / B - 1;

    k1_scan<<<B, 64>>>(draft_probs, target_probs, uniform_probs,
                       draft_token_ids, cu, bonus, out, V, NT, L);
    k2_argmax_slice<<<dim3(S, B), TPB2>>>(target_probs, V);
    k3_finalize<<<B, 32>>>(out, L);
}

// round 4
// speedup vs baseline: 1.1400x; 1.1400x over previous
#include <cuda_runtime.h>
#include <cuda_bf16.h>
#include <cstdint>

#define MAXL 16
#define S    16          // argmax slices per request
#define TPB  256
#define MAXB 1024

// Zero-initialized scratch. g_count is self-resetting (last block per request
// stores 0 after finalizing), so graph replays always start from 0.
__device__ unsigned long long g_slot[MAXB * S];
__device__ int                g_count[MAXB];

__global__ void __launch_bounds__(TPB)
fused_rejection_kernel(
    const float* __restrict__ draft_probs,
    const float* __restrict__ target_probs,
    const float* __restrict__ uniform_probs,
    const int*   __restrict__ draft_token_ids,
    const int*   __restrict__ cu,
    const int*   __restrict__ bonus,
    float*       __restrict__ out,
    int V, int NT, int L)
{
    const int s   = blockIdx.x;   // slice
    const int b   = blockIdx.y;   // request
    const int tid = threadIdx.x;

    __shared__ int   s_dids[MAXL];
    __shared__ float s_tp[MAXL], s_dp[MAXL], s_u[MAXL];
    __shared__ int   s_last, s_rejected, s_write_col, s_recrow;
    __shared__ unsigned long long s_warp[TPB / 32];

    const int prev   = (b == 0) ? 0 : __ldg(&cu[b - 1]);
    const int ndraft = __ldg(&cu[b]) - prev;
    const int n      = ndraft < L ? ndraft : L;

    // Parallel gather (redundant across the 16 slices of a request; replicas
    // hit L2 — the redundancy buys full overlap of this latency chain with
    // the streaming phase below).
    if (tid < n && n > 0) {
        long long gidx = (long long)(prev + tid);
        int d = __ldg(&draft_token_ids[gidx]);
        s_dids[tid] = d;
        s_tp[tid] = __ldg(&target_probs[gidx * (long long)V + d]);
        s_dp[tid] = __ldg(&draft_probs [gidx * (long long)V + d]);
        s_u [tid] = __ldg(&uniform_probs[gidx]);
    }
    __syncthreads();

    if (tid == 0) {
        float pi = 1.0f, U = 1.0f;
        int last = -1;
        for (int i = 0; i < n; i++) {
            float dp = s_dp[i];
            float r  = (dp > 0.0f) ? (s_tp[i] / dp) : 1.0f;
            pi = fminf(pi * r, 1.0f);
            U  = U * s_u[i];
            if ((dp > 0.0f) && (pi >= U)) last = i;
        }
        int rejected = (ndraft > 0) && (last != ndraft - 1);
        int rr = prev + last + 1;
        s_recrow    = max(0, min(rr, NT - 1));
        s_last      = last;
        s_rejected  = rejected;
        s_write_col = rejected ? (last + 1) : n;
    }
    __syncthreads();

    // Slice 0 emits the base output row (recovered slot patched below).
    if (s == 0 && tid <= L) {
        int val = (tid < L && tid <= s_last) ? s_dids[tid] : -1;
        if (tid == s_write_col)
            val = s_rejected ? -1 : __ldg(&bonus[b]);
        out[b * (L + 1) + tid] = (float)val;
    }

    if (!s_rejected) return;

    // ---- streaming argmax over this block's slice of the recovery row ----
    // Key: (float_bits << 32) | (0xFFFFFFFF - idx). Softmax probs >= 0 so the
    // fp32 bit pattern is order-preserving; ties -> smallest index (jnp.argmax).
    const int chunk = (((V + S - 1) / S) + 3) & ~3;
    const int start = s * chunk;
    const int end   = min(V, start + chunk);
    const float* __restrict__ row = target_probs + (long long)s_recrow * V;

    unsigned long long best = 0ull;
    int i = start + tid * 4;
    for (; i + 3 < end; i += TPB * 4) {
        float4 v = *(const float4*)(row + i);
        unsigned long long k;
        k = ((unsigned long long)__float_as_uint(v.x) << 32) | (0xFFFFFFFFu - (unsigned)i);
        if (k > best) best = k;
        k = ((unsigned long long)__float_as_uint(v.y) << 32) | (0xFFFFFFFFu - (unsigned)(i + 1));
        if (k > best) best = k;
        k = ((unsigned long long)__float_as_uint(v.z) << 32) | (0xFFFFFFFFu - (unsigned)(i + 2));
        if (k > best) best = k;
        k = ((unsigned long long)__float_as_uint(v.w) << 32) | (0xFFFFFFFFu - (unsigned)(i + 3));
        if (k > best) best = k;
    }
    for (; i < end; i++) {
        unsigned long long k =
            ((unsigned long long)__float_as_uint(row[i]) << 32) |
            (0xFFFFFFFFu - (unsigned)i);
        if (k > best) best = k;
    }

    #pragma unroll
    for (int off = 16; off > 0; off >>= 1) {
        unsigned long long o = __shfl_down_sync(0xFFFFFFFFu, best, off);
        if (o > best) best = o;
    }
    if ((tid & 31) == 0) s_warp[tid >> 5] = best;
    __syncthreads();

    if (tid < 32) {
        unsigned long long v = (tid < (TPB / 32)) ? s_warp[tid] : 0ull;
        #pragma unroll
        for (int off = 16; off > 0; off >>= 1) {
            unsigned long long o = __shfl_down_sync(0xFFFFFFFFu, v, off);
            if (o > v) v = o;
        }
        if (tid == 0) {
            g_slot[b * S + s] = v;
            __threadfence();
            int old = atomicAdd(&g_count[b], 1);
            if (old == S - 1) {
                // Last block for this request: reduce slots, patch output.
                unsigned long long m = 0ull;
                #pragma unroll
                for (int j = 0; j < S; j++) {
                    unsigned long long w = g_slot[b * S + j];
                    if (w > m) m = w;
                }
                int rec = (int)(0xFFFFFFFFu - (unsigned)(m & 0xFFFFFFFFull));
                out[b * (L + 1) + s_write_col] = (float)rec;
                g_count[b] = 0;           // self-reset for next graph replay
            }
        }
    }
}

extern "C" void kernel_launch(void* const* d_in, const int* in_sizes, int n_in,
                              void* d_out, int out_size) {
    const float* draft_probs     = (const float*)d_in[0];
    const float* target_probs    = (const float*)d_in[1];
    const float* uniform_probs   = (const float*)d_in[2];
    const int*   draft_token_ids = (const int*)  d_in[3];
    const int*   cu              = (const int*)  d_in[4];
    const int*   bonus           = (const int*)  d_in[5];
    float*       out             = (float*)d_out;

    const int NT = in_sizes[2];
    const int V  = in_sizes[0] / NT;
    const int B  = in_sizes[4];
    const int L  = out_size / B - 1;

    fused_rejection_kernel<<<dim3(S, B), TPB>>>(
        draft_probs, target_probs, uniform_probs,
        draft_token_ids, cu, bonus, out, V, NT, L);
}